// round 16
// baseline (speedup 1.0000x reference)
#include <cuda_runtime.h>
#include <cuda_bf16.h>
#include <cstdint>

#define BB 32
#define CH 1024
#define SP 1024
#define CQ 128

// ---------------- scratch ----------------
__device__ uint8_t       g_xT8[(size_t)BB * SP * CH];  // [b][n][c] e4m3
__device__ uint8_t       g_Q8[(size_t)BB * SP * CQ];   // [b][n][o] e4m3
__device__ uint8_t       g_K8[(size_t)BB * SP * CQ];   // [b][m][o] e4m3
__device__ __nv_bfloat16 g_P [(size_t)BB * CH * SP];   // attT[b][m][n] = exp(e[n][m])
__device__ float         g_scale[(size_t)BB * SP];     // gamma / (64 * rowsum[n])
__device__ uint8_t       g_Wq8[CQ * CH];               // e4m3 x64
__device__ uint8_t       g_Wk8[CQ * CH];               // e4m3 x64
__device__ uint8_t       g_Wv8[(size_t)CH * CH];       // e4m3 x64

// ---------------- helpers ----------------
__device__ __forceinline__ uint32_t smem_u32(const void* p) {
    uint32_t a;
    asm("{ .reg .u64 t; cvta.to.shared.u64 t, %1; cvt.u32.u64 %0, t; }" : "=r"(a) : "l"(p));
    return a;
}
#define CP16(d, s) \
    asm volatile("cp.async.cg.shared.global [%0], [%1], 16;" :: "r"(d), "l"(s) : "memory")
#define CP_COMMIT() asm volatile("cp.async.commit_group;" ::: "memory")
#define CP_WAIT0()  asm volatile("cp.async.wait_group 0;" ::: "memory")

#define MBAR_INIT(a, cnt) \
    asm volatile("mbarrier.init.shared.b64 [%0], %1;" :: "r"(a), "r"((uint32_t)(cnt)) : "memory")
#define CPA_ARRIVE(a) \
    asm volatile("cp.async.mbarrier.arrive.noinc.shared.b64 [%0];" :: "r"(a) : "memory")
#define MBAR_ARRIVE(a) \
    asm volatile("mbarrier.arrive.shared.b64 _, [%0];" :: "r"(a) : "memory")
#define MBAR_WAIT(a, ph) do { \
    uint32_t _done = 0; \
    while (!_done) \
        asm volatile("{ .reg .pred p; mbarrier.try_wait.parity.shared.b64 p, [%1], %2; selp.u32 %0, 1, 0, p; }" \
            : "=r"(_done) : "r"(a), "r"((uint32_t)(ph)) : "memory"); \
} while (0)

__device__ __forceinline__ void ldm_x4(uint32_t (&r)[4], uint32_t a) {
    asm volatile("ldmatrix.sync.aligned.m8n8.x4.shared.b16 {%0,%1,%2,%3}, [%4];"
        : "=r"(r[0]), "=r"(r[1]), "=r"(r[2]), "=r"(r[3]) : "r"(a));
}
__device__ __forceinline__ void mma16832q(float (&c)[4], const uint32_t (&a)[4],
                                          uint32_t b0, uint32_t b1) {
    asm volatile(
        "mma.sync.aligned.m16n8k32.row.col.f32.e4m3.e4m3.f32 "
        "{%0,%1,%2,%3}, {%4,%5,%6,%7}, {%8,%9}, {%0,%1,%2,%3};"
        : "+f"(c[0]), "+f"(c[1]), "+f"(c[2]), "+f"(c[3])
        : "r"(a[0]), "r"(a[1]), "r"(a[2]), "r"(a[3]), "r"(b0), "r"(b1));
}
__device__ __forceinline__ float fast_exp(float x) {
    float t = fmaf(x, 12102203.0f, 1064866805.0f);
    return __int_as_float((int)t);
}
__device__ __forceinline__ uint32_t pack_e4m3_4(float a, float b, float c, float d) {
    uint16_t lo, hi;
    asm("cvt.rn.satfinite.e4m3x2.f32 %0, %1, %2;" : "=h"(lo) : "f"(b), "f"(a));
    asm("cvt.rn.satfinite.e4m3x2.f32 %0, %1, %2;" : "=h"(hi) : "f"(d), "f"(c));
    return (uint32_t)lo | ((uint32_t)hi << 16);
}
__device__ __forceinline__ uint16_t pack_e4m3_2(float a, float b) {
    uint16_t v;
    asm("cvt.rn.satfinite.e4m3x2.f32 %0, %1, %2;" : "=h"(v) : "f"(b), "f"(a));
    return v;
}

// ---------------- kernel: convert all weights fp32 -> e4m3 (x64) ----------------
__global__ void k_cvtall(const float* __restrict__ Wq, const float* __restrict__ Wk,
                         const float* __restrict__ Wv) {
    const int QK = CQ * CH;
    int i = (blockIdx.x * 256 + threadIdx.x) * 4;
    const float* s; uint8_t* d; int off;
    if (i < QK)            { s = Wq; d = g_Wq8; off = i; }
    else if (i < 2 * QK)   { s = Wk; d = g_Wk8; off = i - QK; }
    else                   { s = Wv; d = g_Wv8; off = i - 2 * QK; }
    float4 v = *reinterpret_cast<const float4*>(s + off);
    *reinterpret_cast<uint32_t*>(d + off) =
        pack_e4m3_4(v.x * 64.0f, v.y * 64.0f, v.z * 64.0f, v.w * 64.0f);
}

// ---------------- kernel: x[b][c][n] fp32 -> xT8[b][n][c] e4m3 (64x64 tiles) ----------------
__global__ void __launch_bounds__(256) k_transpose(const float* __restrict__ x) {
    __shared__ float ts[64][68];
    const int b = blockIdx.z, c0 = blockIdx.y * 64, n0 = blockIdx.x * 64;
    const int tid = threadIdx.x;
    {
        const int r = tid >> 4, c4 = (tid & 15) * 4;
        const float* src = x + ((size_t)b * CH + c0 + r) * SP + n0 + c4;
#pragma unroll
        for (int u = 0; u < 4; u++) {
            float4 v = *reinterpret_cast<const float4*>(src + (size_t)u * 16 * SP);
            ts[r + u * 16][c4] = v.x; ts[r + u * 16][c4 + 1] = v.y;
            ts[r + u * 16][c4 + 2] = v.z; ts[r + u * 16][c4 + 3] = v.w;
        }
    }
    __syncthreads();
    {
        const int ch = (tid & 7) * 8;
#pragma unroll
        for (int u = 0; u < 2; u++) {
            int nn = (tid >> 3) + u * 32;
            uint2 o8;
            o8.x = pack_e4m3_4(ts[ch][nn],     ts[ch + 1][nn],
                               ts[ch + 2][nn], ts[ch + 3][nn]);
            o8.y = pack_e4m3_4(ts[ch + 4][nn], ts[ch + 5][nn],
                               ts[ch + 6][nn], ts[ch + 7][nn]);
            *reinterpret_cast<uint2*>(
                g_xT8 + ((size_t)b * SP + n0 + nn) * CH + c0 + ch) = o8;
        }
    }
}

// ---------------- FP8 GEMM blocks ----------------
#define STQ 36864
#define MB_OFF 110592
#define GEMM_SMEM 110720
__device__ __forceinline__ void stage128q(uint32_t sdst, const uint8_t* g,
                                          int stride, int tid) {
#pragma unroll
    for (int u = 0; u < 4; u++) {
        int idx = tid + u * 256, r = idx >> 3, c = idx & 7;
        CP16(sdst + r * 144 + c * 16, g + (size_t)r * stride + c * 16);
    }
}
// warp tile: 64 rows (A, via wm) x 32 cols (B rows, via wn); 4 ks covers 128 K-bytes
__device__ __forceinline__ void mma_block128q(uint32_t sA, uint32_t sB,
                                              float (&acc)[4][4][4], int lane, int wm, int wn) {
#pragma unroll
    for (int ks = 0; ks < 4; ks++) {
        uint32_t a[4][4];
#pragma unroll
        for (int i = 0; i < 4; i++)
            ldm_x4(a[i], sA + (wm + i * 16 + (lane & 15)) * 144 + ks * 32 + ((lane >> 4) << 4));
        uint32_t bf[2][4];
#pragma unroll
        for (int jp = 0; jp < 2; jp++)
            ldm_x4(bf[jp], sB + (wn + jp * 16 + ((lane >> 4) << 3) + (lane & 7)) * 144
                              + ks * 32 + (((lane >> 3) & 1) << 4));
#pragma unroll
        for (int i = 0; i < 4; i++)
#pragma unroll
            for (int j = 0; j < 4; j++)
                mma16832q(acc[i][j], a[i], bf[j >> 1][(j & 1) * 2], bf[j >> 1][(j & 1) * 2 + 1]);
    }
}
// R13-proven mbarrier pipeline: 3 stages, all warps stage every chunk, no __syncthreads.
__device__ __forceinline__ void gemm_mb(const uint8_t* Ag, const uint8_t* Bg,
                                        int strideA, int strideB,
                                        uint32_t sb, float (&acc)[4][4][4],
                                        int tid, int lane, int wm, int wn) {
    const uint32_t mb = sb + MB_OFF;   // full[s]=mb+s*8, empty[s]=mb+24+s*8
    if (tid == 0) {
#pragma unroll
        for (int s = 0; s < 3; s++) {
            MBAR_INIT(mb + s * 8, 256);
            MBAR_INIT(mb + 24 + s * 8, 256);
        }
    }
    __syncthreads();   // barriers visible
#pragma unroll
    for (int s = 0; s < 2; s++) {
        stage128q(sb + s * STQ, Ag + (size_t)s * 128, strideA, tid);
        stage128q(sb + s * STQ + 18432, Bg + (size_t)s * 128, strideB, tid);
        CPA_ARRIVE(mb + s * 8);
    }
#pragma unroll 1
    for (int kc = 0; kc < 8; kc++) {
        const int st = kc % 3;
        MBAR_WAIT(mb + st * 8, (kc / 3) & 1);                   // full
        mma_block128q(sb + st * STQ, sb + st * STQ + 18432, acc, lane, wm, wn);
        MBAR_ARRIVE(mb + 24 + st * 8);                          // empty
        const int c = kc + 2;
        if (c < 8) {
            const int s2 = c % 3;
            if (c >= 3) MBAR_WAIT(mb + 24 + s2 * 8, ((c / 3) - 1) & 1);  // stage reusable
            stage128q(sb + s2 * STQ, Ag + (size_t)c * 128, strideA, tid);
            stage128q(sb + s2 * STQ + 18432, Bg + (size_t)c * 128, strideB, tid);
            CPA_ARRIVE(mb + s2 * 8);
        }
    }
}

// ---- 512-thread variant: tile 256(A) x 128(B), same schedule, counts 512 ----
#define STQ2 55296
#define MB2_OFF 165888
#define GEMM2_SMEM 166016
__device__ __forceinline__ void stage512(uint32_t sdst, const uint8_t* gA,
                                         const uint8_t* gB, int strideA,
                                         int strideB, int tid) {
#pragma unroll
    for (int u = 0; u < 4; u++) {          // A: 256 rows x 8 chunks = 2048 CP16
        int idx = tid + u * 512, r = idx >> 3, c = idx & 7;
        CP16(sdst + r * 144 + c * 16, gA + (size_t)r * strideA + c * 16);
    }
#pragma unroll
    for (int u = 0; u < 2; u++) {          // B: 128 rows x 8 chunks = 1024 CP16
        int idx = tid + u * 512, r = idx >> 3, c = idx & 7;
        CP16(sdst + 36864 + r * 144 + c * 16, gB + (size_t)r * strideB + c * 16);
    }
}
__device__ __forceinline__ void gemm_mb512(const uint8_t* Ag, const uint8_t* Bg,
                                           int strideA, int strideB,
                                           uint32_t sb, float (&acc)[4][4][4],
                                           int tid, int lane, int wm, int wn) {
    const uint32_t mb = sb + MB2_OFF;
    if (tid == 0) {
#pragma unroll
        for (int s = 0; s < 3; s++) {
            MBAR_INIT(mb + s * 8, 512);
            MBAR_INIT(mb + 24 + s * 8, 512);
        }
    }
    __syncthreads();
#pragma unroll
    for (int s = 0; s < 2; s++) {
        stage512(sb + s * STQ2, Ag + (size_t)s * 128, Bg + (size_t)s * 128,
                 strideA, strideB, tid);
        CPA_ARRIVE(mb + s * 8);
    }
#pragma unroll 1
    for (int kc = 0; kc < 8; kc++) {
        const int st = kc % 3;
        MBAR_WAIT(mb + st * 8, (kc / 3) & 1);
        mma_block128q(sb + st * STQ2, sb + st * STQ2 + 36864, acc, lane, wm, wn);
        MBAR_ARRIVE(mb + 24 + st * 8);
        const int c = kc + 2;
        if (c < 8) {
            const int s2 = c % 3;
            if (c >= 3) MBAR_WAIT(mb + 24 + s2 * 8, ((c / 3) - 1) & 1);
            stage512(sb + s2 * STQ2, Ag + (size_t)c * 128, Bg + (size_t)c * 128,
                     strideA, strideB, tid);
            CPA_ARRIVE(mb + s2 * 8);
        }
    }
}

// ---------------- kernel: Q & K projection (fp8, R13 mbarrier core) ----------------
__global__ void __launch_bounds__(256, 2) k_proj(const float* __restrict__ bq,
                                                 const float* __restrict__ bk) {
    extern __shared__ char sm[];
    uint32_t sb = smem_u32(sm);
    const int tid = threadIdx.x, lane = tid & 31, wid = tid >> 5;
    const int wm = (wid >> 2) * 64, wn = (wid & 3) * 32;
    const int b = blockIdx.y, r0 = blockIdx.x * 128, which = blockIdx.z;
    const uint8_t* W = which ? g_Wk8 : g_Wq8;
    const float* bias = which ? bk : bq;
    uint8_t* dst = which ? g_K8 : g_Q8;

    float acc[4][4][4];
#pragma unroll
    for (int i = 0; i < 4; i++)
#pragma unroll
        for (int j = 0; j < 4; j++)
#pragma unroll
            for (int k = 0; k < 4; k++) acc[i][j][k] = 0.0f;

    gemm_mb(g_xT8 + ((size_t)b * SP + r0) * CH, W, CH, CH, sb, acc, tid, lane, wm, wn);

#pragma unroll
    for (int j = 0; j < 4; j++) {
        int col = wn + j * 8 + (lane & 3) * 2;
        float b0 = bias[col], b1 = bias[col + 1];
#pragma unroll
        for (int i = 0; i < 4; i++) {
            int rr = r0 + wm + i * 16 + (lane >> 2);
            *reinterpret_cast<uint16_t*>(&dst[((size_t)b * SP + rr) * CQ + col]) =
                pack_e4m3_2(fmaf(acc[i][j][0], 0.015625f, b0),
                            fmaf(acc[i][j][1], 0.015625f, b1));
            *reinterpret_cast<uint16_t*>(&dst[((size_t)b * SP + rr + 8) * CQ + col]) =
                pack_e4m3_2(fmaf(acc[i][j][2], 0.015625f, b0),
                            fmaf(acc[i][j][3], 0.015625f, b1));
        }
    }
}

// ---------------- kernel: energy + softmax (fp8 mainloop, 128-row n-tiles) ----------------
#define ELD 136
#define EB 18432
#define EP 36864
#define ESUM 71680
#define EN_SMEM 72192
__global__ void __launch_bounds__(256, 2) k_energy(const float* __restrict__ gm) {
    extern __shared__ char sm[];
    uint32_t sb = smem_u32(sm);
    float* s_sum = reinterpret_cast<float*>(sm + ESUM);
    __nv_bfloat16* Ps = reinterpret_cast<__nv_bfloat16*>(sm + EP);
    const int tid = threadIdx.x, lane = tid & 31, wid = tid >> 5;
    const int wnn = (wid >> 2) * 64, wmm = (wid & 3) * 32;
    const int b = blockIdx.y, n0 = blockIdx.x * 128;

    if (tid < 128) s_sum[tid] = 0.0f;

    const uint8_t* Qg = g_Q8 + ((size_t)b * SP + n0) * CQ;
    const uint8_t* Kg = g_K8 + (size_t)b * SP * CQ;
    stage128q(sb, Qg, CQ, tid);
    stage128q(sb + EB, Kg, CQ, tid);
    CP_COMMIT();

#pragma unroll 1
    for (int mc = 0; mc < 8; mc++) {
        CP_WAIT0();
        __syncthreads();
        float acc[4][4][4];
#pragma unroll
        for (int i = 0; i < 4; i++)
#pragma unroll
            for (int j = 0; j < 4; j++)
#pragma unroll
                for (int k = 0; k < 4; k++) acc[i][j][k] = 0.0f;
        mma_block128q(sb, sb + EB, acc, lane, wnn, wmm);
        __syncthreads();
        if (mc < 7) {
            stage128q(sb + EB, Kg + (size_t)(mc + 1) * 128 * CQ, CQ, tid);
            CP_COMMIT();
        }
#pragma unroll
        for (int i = 0; i < 4; i++) {
            int nA = wnn + i * 16 + (lane >> 2), nB = nA + 8;
            float s0 = 0.0f, s1 = 0.0f;
#pragma unroll
            for (int j = 0; j < 4; j++) {
                int mcol = wmm + j * 8 + (lane & 3) * 2;
                float p0 = fast_exp(acc[i][j][0]), p1 = fast_exp(acc[i][j][1]);
                float p2 = fast_exp(acc[i][j][2]), p3 = fast_exp(acc[i][j][3]);
                s0 += p0 + p1; s1 += p2 + p3;
                Ps[(size_t)mcol * ELD + nA]       = __float2bfloat16(p0);
                Ps[(size_t)(mcol + 1) * ELD + nA] = __float2bfloat16(p1);
                Ps[(size_t)mcol * ELD + nB]       = __float2bfloat16(p2);
                Ps[(size_t)(mcol + 1) * ELD + nB] = __float2bfloat16(p3);
            }
            s0 += __shfl_xor_sync(0xffffffffu, s0, 1);
            s0 += __shfl_xor_sync(0xffffffffu, s0, 2);
            s1 += __shfl_xor_sync(0xffffffffu, s1, 1);
            s1 += __shfl_xor_sync(0xffffffffu, s1, 2);
            if ((lane & 3) == 0) { atomicAdd(&s_sum[nA], s0); atomicAdd(&s_sum[nB], s1); }
        }
        __syncthreads();
#pragma unroll
        for (int u = 0; u < 8; u++) {
            int idx = tid + u * 256, r = idx >> 4, c = idx & 15;
            uint4 v = *reinterpret_cast<uint4*>(sm + EP + r * 272 + c * 16);
            *reinterpret_cast<uint4*>(
                &g_P[((size_t)b * CH + mc * 128 + r) * SP + n0 + c * 8]) = v;
        }
    }
    __syncthreads();
    if (tid < 128)   // 1/64 folds the fp8 weight scaling used in k_vapply
        g_scale[(size_t)b * SP + n0 + tid] = gm[0] * 0.015625f / s_sum[tid];
}

// ---------------- kernel: V GEMM fp8, 512 threads, 256x128 tile, fused apply ----------
__global__ void __launch_bounds__(512, 1) k_vapply(const float* __restrict__ bv,
                                                   const float* __restrict__ x,
                                                   float* __restrict__ out) {
    extern __shared__ char sm[];
    uint32_t sb = smem_u32(sm);
    const int tid = threadIdx.x, lane = tid & 31, wid = tid >> 5;
    const int wm = (wid >> 2) * 64, wn = (wid & 3) * 32;   // 4 m-groups x 4 n-groups
    const int b = blockIdx.z, m0 = blockIdx.y * 256, n0 = blockIdx.x * 128;

    float acc[4][4][4];
#pragma unroll
    for (int i = 0; i < 4; i++)
#pragma unroll
        for (int j = 0; j < 4; j++)
#pragma unroll
            for (int k = 0; k < 4; k++) acc[i][j][k] = 0.0f;

    gemm_mb512(g_Wv8 + (size_t)m0 * CH, g_xT8 + ((size_t)b * SP + n0) * CH,
               CH, CH, sb, acc, tid, lane, wm, wn);

#pragma unroll
    for (int i = 0; i < 4; i++) {
        int mA = m0 + wm + i * 16 + (lane >> 2), mB = mA + 8;
        float bvA = bv[mA] * 64.0f, bvB = bv[mB] * 64.0f;   // g_scale carries the 1/64
#pragma unroll
        for (int j = 0; j < 4; j++) {
            int n = n0 + wn + j * 8 + (lane & 3) * 2;
            size_t pa = ((size_t)b * CH + mA) * SP + n;
            size_t pb = ((size_t)b * CH + mB) * SP + n;
            float2 sc = *reinterpret_cast<const float2*>(&g_scale[(size_t)b * SP + n]);
            __nv_bfloat162 PA = *reinterpret_cast<const __nv_bfloat162*>(&g_P[pa]);
            __nv_bfloat162 PB = *reinterpret_cast<const __nv_bfloat162*>(&g_P[pb]);
            float2 xa = *reinterpret_cast<const float2*>(&x[pa]);
            float2 xb = *reinterpret_cast<const float2*>(&x[pb]);
            float2 oa, ob;
            oa.x = fmaf((acc[i][j][0] + bvA) * __bfloat162float(PA.x), sc.x, xa.x);
            oa.y = fmaf((acc[i][j][1] + bvA) * __bfloat162float(PA.y), sc.y, xa.y);
            ob.x = fmaf((acc[i][j][2] + bvB) * __bfloat162float(PB.x), sc.x, xb.x);
            ob.y = fmaf((acc[i][j][3] + bvB) * __bfloat162float(PB.y), sc.y, xb.y);
            *reinterpret_cast<float2*>(&out[pa]) = oa;
            *reinterpret_cast<float2*>(&out[pb]) = ob;
        }
    }
}

// ---------------- launcher ----------------
extern "C" void kernel_launch(void* const* d_in, const int* in_sizes, int n_in,
                              void* d_out, int out_size) {
    const float* x  = (const float*)d_in[0];
    const float* Wq = (const float*)d_in[1];
    const float* bq = (const float*)d_in[2];
    const float* Wk = (const float*)d_in[3];
    const float* bk = (const float*)d_in[4];
    const float* Wv = (const float*)d_in[5];
    const float* bv = (const float*)d_in[6];
    const float* gm = (const float*)d_in[7];
    float* out = (float*)d_out;

    cudaFuncSetAttribute(k_proj,   cudaFuncAttributeMaxDynamicSharedMemorySize, GEMM_SMEM);
    cudaFuncSetAttribute(k_vapply, cudaFuncAttributeMaxDynamicSharedMemorySize, GEMM2_SMEM);
    cudaFuncSetAttribute(k_energy, cudaFuncAttributeMaxDynamicSharedMemorySize, EN_SMEM);

    k_cvtall<<<(2 * CQ * CH + CH * CH) / 1024, 256>>>(Wq, Wk, Wv);
    k_transpose<<<dim3(SP / 64, CH / 64, BB), 256>>>(x);
    k_proj<<<dim3(8, BB, 2), 256, GEMM_SMEM>>>(bq, bk);
    k_energy<<<dim3(8, BB), 256, EN_SMEM>>>(gm);
    k_vapply<<<dim3(SP / 128, CH / 256, BB), 512, GEMM2_SMEM>>>(bv, x, out);
}

// round 17
// speedup vs baseline: 1.0670x; 1.0670x over previous
#include <cuda_runtime.h>
#include <cuda_bf16.h>
#include <cstdint>

#define BB 32
#define CH 1024
#define SP 1024
#define CQ 128

// ---------------- scratch ----------------
__device__ uint8_t       g_xT8[(size_t)BB * SP * CH];  // [b][n][c] e4m3
__device__ uint8_t       g_Q8[(size_t)BB * SP * CQ];   // [b][n][o] e4m3
__device__ uint8_t       g_K8[(size_t)BB * SP * CQ];   // [b][m][o] e4m3
__device__ __nv_bfloat16 g_P [(size_t)BB * CH * SP];   // attT[b][m][n] = exp(e[n][m])
__device__ float         g_scale[(size_t)BB * SP];     // gamma / (64 * rowsum[n])
__device__ uint8_t       g_Wq8[CQ * CH];               // e4m3 x64
__device__ uint8_t       g_Wk8[CQ * CH];               // e4m3 x64
__device__ uint8_t       g_Wv8[(size_t)CH * CH];       // e4m3 x64

// ---------------- helpers ----------------
__device__ __forceinline__ uint32_t smem_u32(const void* p) {
    uint32_t a;
    asm("{ .reg .u64 t; cvta.to.shared.u64 t, %1; cvt.u32.u64 %0, t; }" : "=r"(a) : "l"(p));
    return a;
}
#define CP16(d, s) \
    asm volatile("cp.async.cg.shared.global [%0], [%1], 16;" :: "r"(d), "l"(s) : "memory")
#define CP_COMMIT() asm volatile("cp.async.commit_group;" ::: "memory")

#define MBAR_INIT(a, cnt) \
    asm volatile("mbarrier.init.shared.b64 [%0], %1;" :: "r"(a), "r"((uint32_t)(cnt)) : "memory")
#define CPA_ARRIVE(a) \
    asm volatile("cp.async.mbarrier.arrive.noinc.shared.b64 [%0];" :: "r"(a) : "memory")
#define MBAR_ARRIVE(a) \
    asm volatile("mbarrier.arrive.shared.b64 _, [%0];" :: "r"(a) : "memory")
#define MBAR_WAIT(a, ph) do { \
    uint32_t _done = 0; \
    while (!_done) \
        asm volatile("{ .reg .pred p; mbarrier.try_wait.parity.shared.b64 p, [%1], %2; selp.u32 %0, 1, 0, p; }" \
            : "=r"(_done) : "r"(a), "r"((uint32_t)(ph)) : "memory"); \
} while (0)

__device__ __forceinline__ void ldm_x4(uint32_t (&r)[4], uint32_t a) {
    asm volatile("ldmatrix.sync.aligned.m8n8.x4.shared.b16 {%0,%1,%2,%3}, [%4];"
        : "=r"(r[0]), "=r"(r[1]), "=r"(r[2]), "=r"(r[3]) : "r"(a));
}
__device__ __forceinline__ void mma16832q(float (&c)[4], const uint32_t (&a)[4],
                                          uint32_t b0, uint32_t b1) {
    asm volatile(
        "mma.sync.aligned.m16n8k32.row.col.f32.e4m3.e4m3.f32 "
        "{%0,%1,%2,%3}, {%4,%5,%6,%7}, {%8,%9}, {%0,%1,%2,%3};"
        : "+f"(c[0]), "+f"(c[1]), "+f"(c[2]), "+f"(c[3])
        : "r"(a[0]), "r"(a[1]), "r"(a[2]), "r"(a[3]), "r"(b0), "r"(b1));
}
__device__ __forceinline__ float fast_exp(float x) {
    float t = fmaf(x, 12102203.0f, 1064866805.0f);
    return __int_as_float((int)t);
}
__device__ __forceinline__ uint32_t pack_e4m3_4(float a, float b, float c, float d) {
    uint16_t lo, hi;
    asm("cvt.rn.satfinite.e4m3x2.f32 %0, %1, %2;" : "=h"(lo) : "f"(b), "f"(a));
    asm("cvt.rn.satfinite.e4m3x2.f32 %0, %1, %2;" : "=h"(hi) : "f"(d), "f"(c));
    return (uint32_t)lo | ((uint32_t)hi << 16);
}
__device__ __forceinline__ uint16_t pack_e4m3_2(float a, float b) {
    uint16_t v;
    asm("cvt.rn.satfinite.e4m3x2.f32 %0, %1, %2;" : "=h"(v) : "f"(b), "f"(a));
    return v;
}

// ---------------- kernel: convert all weights fp32 -> e4m3 (x64) ----------------
__global__ void k_cvtall(const float* __restrict__ Wq, const float* __restrict__ Wk,
                         const float* __restrict__ Wv) {
    const int QK = CQ * CH;
    int i = (blockIdx.x * 256 + threadIdx.x) * 4;
    const float* s; uint8_t* d; int off;
    if (i < QK)            { s = Wq; d = g_Wq8; off = i; }
    else if (i < 2 * QK)   { s = Wk; d = g_Wk8; off = i - QK; }
    else                   { s = Wv; d = g_Wv8; off = i - 2 * QK; }
    float4 v = *reinterpret_cast<const float4*>(s + off);
    *reinterpret_cast<uint32_t*>(d + off) =
        pack_e4m3_4(v.x * 64.0f, v.y * 64.0f, v.z * 64.0f, v.w * 64.0f);
}

// ---------------- kernel: x[b][c][n] fp32 -> xT8[b][n][c] e4m3 (64x64 tiles) ----------------
__global__ void __launch_bounds__(256) k_transpose(const float* __restrict__ x) {
    __shared__ float ts[64][68];
    const int b = blockIdx.z, c0 = blockIdx.y * 64, n0 = blockIdx.x * 64;
    const int tid = threadIdx.x;
    {
        const int r = tid >> 4, c4 = (tid & 15) * 4;
        const float* src = x + ((size_t)b * CH + c0 + r) * SP + n0 + c4;
#pragma unroll
        for (int u = 0; u < 4; u++) {
            float4 v = *reinterpret_cast<const float4*>(src + (size_t)u * 16 * SP);
            ts[r + u * 16][c4] = v.x; ts[r + u * 16][c4 + 1] = v.y;
            ts[r + u * 16][c4 + 2] = v.z; ts[r + u * 16][c4 + 3] = v.w;
        }
    }
    __syncthreads();
    {
        const int ch = (tid & 7) * 8;
#pragma unroll
        for (int u = 0; u < 2; u++) {
            int nn = (tid >> 3) + u * 32;
            uint2 o8;
            o8.x = pack_e4m3_4(ts[ch][nn],     ts[ch + 1][nn],
                               ts[ch + 2][nn], ts[ch + 3][nn]);
            o8.y = pack_e4m3_4(ts[ch + 4][nn], ts[ch + 5][nn],
                               ts[ch + 6][nn], ts[ch + 7][nn]);
            *reinterpret_cast<uint2*>(
                g_xT8 + ((size_t)b * SP + n0 + nn) * CH + c0 + ch) = o8;
        }
    }
}

// ---------------- FP8 GEMM blocks (R13-proven) ----------------
#define STQ 36864
#define MB_OFF 110592
#define GEMM_SMEM 110720
__device__ __forceinline__ void stage128q(uint32_t sdst, const uint8_t* g,
                                          int stride, int tid) {
#pragma unroll
    for (int u = 0; u < 4; u++) {
        int idx = tid + u * 256, r = idx >> 3, c = idx & 7;
        CP16(sdst + r * 144 + c * 16, g + (size_t)r * stride + c * 16);
    }
}
// warp tile: 64 rows (A, via wm) x 32 cols (B rows, via wn); 4 ks covers 128 K-bytes
__device__ __forceinline__ void mma_block128q(uint32_t sA, uint32_t sB,
                                              float (&acc)[4][4][4], int lane, int wm, int wn) {
#pragma unroll
    for (int ks = 0; ks < 4; ks++) {
        uint32_t a[4][4];
#pragma unroll
        for (int i = 0; i < 4; i++)
            ldm_x4(a[i], sA + (wm + i * 16 + (lane & 15)) * 144 + ks * 32 + ((lane >> 4) << 4));
        uint32_t bf[2][4];
#pragma unroll
        for (int jp = 0; jp < 2; jp++)
            ldm_x4(bf[jp], sB + (wn + jp * 16 + ((lane >> 4) << 3) + (lane & 7)) * 144
                              + ks * 32 + (((lane >> 3) & 1) << 4));
#pragma unroll
        for (int i = 0; i < 4; i++)
#pragma unroll
            for (int j = 0; j < 4; j++)
                mma16832q(acc[i][j], a[i], bf[j >> 1][(j & 1) * 2], bf[j >> 1][(j & 1) * 2 + 1]);
    }
}
// R13-proven mbarrier pipeline: 3 stages, all warps stage every chunk, no __syncthreads.
__device__ __forceinline__ void gemm_mb(const uint8_t* Ag, const uint8_t* Bg,
                                        int strideA, int strideB,
                                        uint32_t sb, float (&acc)[4][4][4],
                                        int tid, int lane, int wm, int wn) {
    const uint32_t mb = sb + MB_OFF;   // full[s]=mb+s*8, empty[s]=mb+24+s*8
    if (tid == 0) {
#pragma unroll
        for (int s = 0; s < 3; s++) {
            MBAR_INIT(mb + s * 8, 256);
            MBAR_INIT(mb + 24 + s * 8, 256);
        }
    }
    __syncthreads();   // barriers visible
#pragma unroll
    for (int s = 0; s < 2; s++) {
        stage128q(sb + s * STQ, Ag + (size_t)s * 128, strideA, tid);
        stage128q(sb + s * STQ + 18432, Bg + (size_t)s * 128, strideB, tid);
        CPA_ARRIVE(mb + s * 8);
    }
#pragma unroll 1
    for (int kc = 0; kc < 8; kc++) {
        const int st = kc % 3;
        MBAR_WAIT(mb + st * 8, (kc / 3) & 1);                   // full
        mma_block128q(sb + st * STQ, sb + st * STQ + 18432, acc, lane, wm, wn);
        MBAR_ARRIVE(mb + 24 + st * 8);                          // empty
        const int c = kc + 2;
        if (c < 8) {
            const int s2 = c % 3;
            if (c >= 3) MBAR_WAIT(mb + 24 + s2 * 8, ((c / 3) - 1) & 1);  // stage reusable
            stage128q(sb + s2 * STQ, Ag + (size_t)c * 128, strideA, tid);
            stage128q(sb + s2 * STQ + 18432, Bg + (size_t)c * 128, strideB, tid);
            CPA_ARRIVE(mb + s2 * 8);
        }
    }
}

// ---------------- kernel: Q & K projection (fp8, R13 mbarrier core) ----------------
__global__ void __launch_bounds__(256, 2) k_proj(const float* __restrict__ bq,
                                                 const float* __restrict__ bk) {
    extern __shared__ char sm[];
    uint32_t sb = smem_u32(sm);
    const int tid = threadIdx.x, lane = tid & 31, wid = tid >> 5;
    const int wm = (wid >> 2) * 64, wn = (wid & 3) * 32;
    const int b = blockIdx.y, r0 = blockIdx.x * 128, which = blockIdx.z;
    const uint8_t* W = which ? g_Wk8 : g_Wq8;
    const float* bias = which ? bk : bq;
    uint8_t* dst = which ? g_K8 : g_Q8;

    float acc[4][4][4];
#pragma unroll
    for (int i = 0; i < 4; i++)
#pragma unroll
        for (int j = 0; j < 4; j++)
#pragma unroll
            for (int k = 0; k < 4; k++) acc[i][j][k] = 0.0f;

    gemm_mb(g_xT8 + ((size_t)b * SP + r0) * CH, W, CH, CH, sb, acc, tid, lane, wm, wn);

#pragma unroll
    for (int j = 0; j < 4; j++) {
        int col = wn + j * 8 + (lane & 3) * 2;
        float b0 = bias[col], b1 = bias[col + 1];
#pragma unroll
        for (int i = 0; i < 4; i++) {
            int rr = r0 + wm + i * 16 + (lane >> 2);
            *reinterpret_cast<uint16_t*>(&dst[((size_t)b * SP + rr) * CQ + col]) =
                pack_e4m3_2(fmaf(acc[i][j][0], 0.015625f, b0),
                            fmaf(acc[i][j][1], 0.015625f, b1));
            *reinterpret_cast<uint16_t*>(&dst[((size_t)b * SP + rr + 8) * CQ + col]) =
                pack_e4m3_2(fmaf(acc[i][j][2], 0.015625f, b0),
                            fmaf(acc[i][j][3], 0.015625f, b1));
        }
    }
}

// ---------------- kernel: energy + softmax v2 ----------------
// Computes eT = K * Q^T directly: D[m][n] = sum_o K[m][o] Q[n][o] = e[n][m].
// Accumulator is already attT layout -> exp stores straight to g_P (no smem
// transpose, no per-tile __syncthreads). K m-chunks run the R13 mbarrier
// pipeline; Q is staged once (folded into chunk 0's full barrier).
// smem: Q @0 (18432), K stages @18432 (3x18432), mbars @73728, sums @73792
#define E_K 18432
#define E_MB 73728
#define E_SUM 73792
#define EN_SMEM 74304
__global__ void __launch_bounds__(256, 2) k_energy(const float* __restrict__ gm) {
    extern __shared__ char sm[];
    uint32_t sb = smem_u32(sm);
    float* s_sum = reinterpret_cast<float*>(sm + E_SUM);
    const int tid = threadIdx.x, lane = tid & 31, wid = tid >> 5;
    const int wm = (wid >> 2) * 64, wn = (wid & 3) * 32;  // wm: K rows (m), wn: Q rows (n)
    const int b = blockIdx.y, n0 = blockIdx.x * 128;

    if (tid < 128) s_sum[tid] = 0.0f;
    const uint32_t mb = sb + E_MB;
    if (tid == 0) {
#pragma unroll
        for (int s = 0; s < 3; s++) {
            MBAR_INIT(mb + s * 8, 256);
            MBAR_INIT(mb + 24 + s * 8, 256);
        }
    }
    __syncthreads();

    const uint8_t* Qg = g_Q8 + ((size_t)b * SP + n0) * CQ;
    const uint8_t* Kg = g_K8 + (size_t)b * SP * CQ;
    // Q staged once; its cp.asyncs are tracked by chunk 0's CPA_ARRIVE
    stage128q(sb, Qg, CQ, tid);
    stage128q(sb + E_K, Kg, CQ, tid);
    CPA_ARRIVE(mb);
    stage128q(sb + E_K + STQ / 2, Kg + (size_t)128 * CQ, CQ, tid);  // stage 1 @ E_K+18432
    CPA_ARRIVE(mb + 8);

#pragma unroll 1
    for (int mc = 0; mc < 8; mc++) {
        const int st = mc % 3;
        MBAR_WAIT(mb + st * 8, (mc / 3) & 1);
        float acc[4][4][4];
#pragma unroll
        for (int i = 0; i < 4; i++)
#pragma unroll
            for (int j = 0; j < 4; j++)
#pragma unroll
                for (int k = 0; k < 4; k++) acc[i][j][k] = 0.0f;
        // A = K chunk (m rows), B = Q (n rows)
        mma_block128q(sb + E_K + st * 18432, sb, acc, lane, wm, wn);
        MBAR_ARRIVE(mb + 24 + st * 8);
        const int c = mc + 2;
        if (c < 8) {
            const int s2 = c % 3;
            if (c >= 3) MBAR_WAIT(mb + 24 + s2 * 8, ((c / 3) - 1) & 1);
            stage128q(sb + E_K + s2 * 18432, Kg + (size_t)c * 128 * CQ, CQ, tid);
            CPA_ARRIVE(mb + s2 * 8);
        }
        // epilogue: exp -> g_P directly (rows m, cols n: already attT layout)
#pragma unroll
        for (int j = 0; j < 4; j++) {
            const int nloc = wn + j * 8 + (lane & 3) * 2;
            float sj0 = 0.0f, sj1 = 0.0f;
#pragma unroll
            for (int i = 0; i < 4; i++) {
                int mrow = mc * 128 + wm + i * 16 + (lane >> 2);
                float p0 = fast_exp(acc[i][j][0]), p1 = fast_exp(acc[i][j][1]);
                float p2 = fast_exp(acc[i][j][2]), p3 = fast_exp(acc[i][j][3]);
                sj0 += p0 + p2; sj1 += p1 + p3;
                *reinterpret_cast<__nv_bfloat162*>(
                    &g_P[((size_t)b * CH + mrow) * SP + n0 + nloc]) =
                    __floats2bfloat162_rn(p0, p1);
                *reinterpret_cast<__nv_bfloat162*>(
                    &g_P[((size_t)b * CH + mrow + 8) * SP + n0 + nloc]) =
                    __floats2bfloat162_rn(p2, p3);
            }
            sj0 += __shfl_xor_sync(0xffffffffu, sj0, 4);
            sj0 += __shfl_xor_sync(0xffffffffu, sj0, 8);
            sj0 += __shfl_xor_sync(0xffffffffu, sj0, 16);
            sj1 += __shfl_xor_sync(0xffffffffu, sj1, 4);
            sj1 += __shfl_xor_sync(0xffffffffu, sj1, 8);
            sj1 += __shfl_xor_sync(0xffffffffu, sj1, 16);
            if (lane < 4) {
                atomicAdd(&s_sum[wn + j * 8 + lane * 2], sj0);
                atomicAdd(&s_sum[wn + j * 8 + lane * 2 + 1], sj1);
            }
        }
    }
    __syncthreads();
    if (tid < 128)   // 1/64 folds the fp8 weight scaling used in k_vapply
        g_scale[(size_t)b * SP + n0 + tid] = gm[0] * 0.015625f / s_sum[tid];
}

// ---------------- kernel: V GEMM fp8 (R13 mbarrier core) fused with apply ----------------
__global__ void __launch_bounds__(256, 2) k_vapply(const float* __restrict__ bv,
                                                   const float* __restrict__ x,
                                                   float* __restrict__ out) {
    extern __shared__ char sm[];
    uint32_t sb = smem_u32(sm);
    const int tid = threadIdx.x, lane = tid & 31, wid = tid >> 5;
    const int wm = (wid >> 2) * 64, wn = (wid & 3) * 32;
    const int b = blockIdx.z, m0 = blockIdx.y * 128, n0 = blockIdx.x * 128;

    float acc[4][4][4];
#pragma unroll
    for (int i = 0; i < 4; i++)
#pragma unroll
        for (int j = 0; j < 4; j++)
#pragma unroll
            for (int k = 0; k < 4; k++) acc[i][j][k] = 0.0f;

    gemm_mb(g_Wv8 + (size_t)m0 * CH, g_xT8 + ((size_t)b * SP + n0) * CH,
            CH, CH, sb, acc, tid, lane, wm, wn);

#pragma unroll
    for (int i = 0; i < 4; i++) {
        int mA = m0 + wm + i * 16 + (lane >> 2), mB = mA + 8;
        float bvA = bv[mA] * 64.0f, bvB = bv[mB] * 64.0f;   // g_scale carries the 1/64
#pragma unroll
        for (int j = 0; j < 4; j++) {
            int n = n0 + wn + j * 8 + (lane & 3) * 2;
            size_t pa = ((size_t)b * CH + mA) * SP + n;
            size_t pb = ((size_t)b * CH + mB) * SP + n;
            float2 sc = *reinterpret_cast<const float2*>(&g_scale[(size_t)b * SP + n]);
            __nv_bfloat162 PA = *reinterpret_cast<const __nv_bfloat162*>(&g_P[pa]);
            __nv_bfloat162 PB = *reinterpret_cast<const __nv_bfloat162*>(&g_P[pb]);
            float2 xa = *reinterpret_cast<const float2*>(&x[pa]);
            float2 xb = *reinterpret_cast<const float2*>(&x[pb]);
            float2 oa, ob;
            oa.x = fmaf((acc[i][j][0] + bvA) * __bfloat162float(PA.x), sc.x, xa.x);
            oa.y = fmaf((acc[i][j][1] + bvA) * __bfloat162float(PA.y), sc.y, xa.y);
            ob.x = fmaf((acc[i][j][2] + bvB) * __bfloat162float(PB.x), sc.x, xb.x);
            ob.y = fmaf((acc[i][j][3] + bvB) * __bfloat162float(PB.y), sc.y, xb.y);
            *reinterpret_cast<float2*>(&out[pa]) = oa;
            *reinterpret_cast<float2*>(&out[pb]) = ob;
        }
    }
}

// ---------------- launcher ----------------
extern "C" void kernel_launch(void* const* d_in, const int* in_sizes, int n_in,
                              void* d_out, int out_size) {
    const float* x  = (const float*)d_in[0];
    const float* Wq = (const float*)d_in[1];
    const float* bq = (const float*)d_in[2];
    const float* Wk = (const float*)d_in[3];
    const float* bk = (const float*)d_in[4];
    const float* Wv = (const float*)d_in[5];
    const float* bv = (const float*)d_in[6];
    const float* gm = (const float*)d_in[7];
    float* out = (float*)d_out;

    cudaFuncSetAttribute(k_proj,   cudaFuncAttributeMaxDynamicSharedMemorySize, GEMM_SMEM);
    cudaFuncSetAttribute(k_vapply, cudaFuncAttributeMaxDynamicSharedMemorySize, GEMM_SMEM);
    cudaFuncSetAttribute(k_energy, cudaFuncAttributeMaxDynamicSharedMemorySize, EN_SMEM);

    k_cvtall<<<(2 * CQ * CH + CH * CH) / 1024, 256>>>(Wq, Wk, Wv);
    k_transpose<<<dim3(SP / 64, CH / 64, BB), 256>>>(x);
    k_proj<<<dim3(8, BB, 2), 256, GEMM_SMEM>>>(bq, bk);
    k_energy<<<dim3(8, BB), 256, EN_SMEM>>>(gm);
    k_vapply<<<dim3(8, 8, BB), 256, GEMM_SMEM>>>(bv, x, out);
}